// round 11
// baseline (speedup 1.0000x reference)
#include <cuda_runtime.h>
#include <cuda_fp16.h>

#define B        64
#define NV       100000
#define NE       (3 * NV)        // 300000 floats per batch row
#define NT       200000          // tets
#define VOL_BLOCKS 1184          // 8 blocks/SM * 148 SMs
#define E_TILE   128
#define T_TILES  ((NE + E_TILE - 1) / E_TILE)   // 2344 (last tile: 96 rows)
#define P_BLOCKS ((NT + 255) / 256)             // 782 prep blocks
#define S_TILES  ((NE + 63) / 64)               // 4688 scale tiles

// xt stores x * 2^13 (keeps tiny values out of half-denormal range; exact
// power-of-2 so volume can descale losslessly and g_inv absorbs the factor)
#define XT_SCALE    8192.0f
#define XT_INV      (1.0f / 8192.0f)

// Scratch (static device globals — no runtime allocation)
__device__ __half    g_xt[B * NE];               // transposed fp16: xt[e*64 + b] = x*2^13
__device__ int4      g_off4[NT];                 // {o0,o1,o2,pad}, o = idx*192
__device__ float     g_part[B * VOL_BLOCKS];     // partials, [b][blk] transposed
__device__ float     g_inv[B];                   // s_true / 2^13
__device__ unsigned  g_count = 0;                // last-block counter (self-resetting)

// ---------------------------------------------------------------------------
// Kernel 0 (heterogeneous): blocks [0, T_TILES) transpose+convert x -> xt
// (128e x 64b tiles, 8 LDG.128/thread, conflict-light STS);
// blocks [T_TILES, ...) convert M -> fused int4 offsets.
// ---------------------------------------------------------------------------
__global__ void k_pt(const float* __restrict__ x, const void* __restrict__ Mv) {
    const int tid = threadIdx.x;              // 256 threads

    if (blockIdx.x < T_TILES) {
        __shared__ float tile[64][129];       // [b][e_local]
        const int e0 = blockIdx.x * E_TILE;

        // load: 2048 tasks. Warp = 4 b-rows x 32 consecutive floats
        // -> 4 coalesced 128B segments; STS lanes hit distinct banks.
        #pragma unroll
        for (int k = 0; k < 8; k++) {
            int task = tid + k * 256;
            int c4 = (task & 7) | (((task >> 5) & 3) << 3);         // 0..31
            int b  = ((task >> 3) & 3) | (((task >> 7) & 15) << 2); // 0..63
            int e  = e0 + 4 * c4;
            if (e < NE) {
                float4 v = *(const float4*)(x + b * NE + e);
                tile[b][4 * c4 + 0] = v.x;
                tile[b][4 * c4 + 1] = v.y;
                tile[b][4 * c4 + 2] = v.z;
                tile[b][4 * c4 + 3] = v.w;
            }
        }
        __syncthreads();
        // store: 1024 tasks = 128 e x 8 chunks of 8 halves along b
        #pragma unroll
        for (int k = 0; k < 4; k++) {
            int task = tid + k * 256;
            int e = task >> 3;                // 0..127
            int c = task & 7;
            if (e0 + e < NE) {
                __half2 h[4];
                #pragma unroll
                for (int j = 0; j < 4; j++)
                    h[j] = __floats2half2_rn(tile[8 * c + 2 * j][e] * XT_SCALE,
                                             tile[8 * c + 2 * j + 1][e] * XT_SCALE);
                ((int4*)(g_xt + (e0 + e) * B))[c] = *(int4*)h;
            }
        }
    } else {
        // ---------------- index-prep path ----------------
        __shared__ int s_is64;
        if (tid == 0) {
            const int* Mi = (const int*)Mv;
            int nz = 0;
            #pragma unroll
            for (int k = 0; k < 32; k++) nz |= Mi[2 * k + 1];
            s_is64 = (nz == 0);
        }
        __syncthreads();
        int t = (blockIdx.x - T_TILES) * 256 + tid;
        if (t >= NT) return;
        int i0, i1, i2;
        if (s_is64) {
            const long long* Ml = (const long long*)Mv;
            i0 = (int)Ml[3 * t]; i1 = (int)Ml[3 * t + 1]; i2 = (int)Ml[3 * t + 2];
        } else {
            const int* Mi = (const int*)Mv;
            i0 = Mi[3 * t]; i1 = Mi[3 * t + 1]; i2 = Mi[3 * t + 2];
        }
        g_off4[t] = make_int4(i0 * (3 * B), i1 * (3 * B), i2 * (3 * B), 0);
    }
}

// ---------------------------------------------------------------------------
// Kernel 1: per-batch |det| partial sums + fused last-block reduce.
// Loads descale by exact 2^-13 (1 HMUL2/operand) -> identical values to the
// unscaled-half path. det in half2, fp32 accumulation.
// ---------------------------------------------------------------------------
__global__ void k_volume() {
    const int tid  = threadIdx.x;
    const int lane = tid & 31;                // batch-pair id
    const int sub  = tid >> 5;                // tet stream 0..7
    const __half2 hds = __float2half2_rn(XT_INV);

    float2 acc = make_float2(0.0f, 0.0f);
    const int stride = VOL_BLOCKS * 8;
    #pragma unroll 4
    for (int t = blockIdx.x * 8 + sub; t < NT; t += stride) {
        const int4 o = __ldg(&g_off4[t]);

        const __half2* p0 = (const __half2*)(g_xt + o.x) + lane;
        const __half2* p1 = (const __half2*)(g_xt + o.y) + lane;
        const __half2* p2 = (const __half2*)(g_xt + o.z) + lane;

        __half2 ax = __hmul2(p0[0], hds), ay = __hmul2(p0[32], hds), az = __hmul2(p0[64], hds);
        __half2 bx = __hmul2(p1[0], hds), by = __hmul2(p1[32], hds), bz = __hmul2(p1[64], hds);
        __half2 cx = __hmul2(p2[0], hds), cy = __hmul2(p2[32], hds), cz = __hmul2(p2[64], hds);

        __half2 nbz = __hneg2(bz);
        __half2 m0 = __hfma2(by, cz, __hmul2(nbz, cy));         // by*cz - bz*cy
        __half2 m1 = __hfma2(bx, cz, __hmul2(nbz, cx));         // bx*cz - bz*cx
        __half2 m2 = __hfma2(bx, cy, __hmul2(__hneg2(by), cx)); // bx*cy - by*cx

        __half2 det = __hmul2(ax, m0);
        det = __hfma2(__hneg2(ay), m1, det);
        det = __hfma2(az, m2, det);
        det = __habs2(det);

        float2 f = __half22float2(det);
        acc.x += f.x;
        acc.y += f.y;
    }

    __shared__ float2 sred[8][32];
    sred[sub][lane] = acc;
    __syncthreads();
    if (sub == 0) {
        float2 s = acc;
        #pragma unroll
        for (int r = 1; r < 8; r++) {
            s.x += sred[r][lane].x;
            s.y += sred[r][lane].y;
        }
        g_part[(2 * lane + 0) * VOL_BLOCKS + blockIdx.x] = s.x;
        g_part[(2 * lane + 1) * VOL_BLOCKS + blockIdx.x] = s.y;
    }

    // ---- fused deterministic reduce in the last block to finish ----
    __shared__ int s_last;
    if (tid == 0) {
        __threadfence();
        unsigned c = atomicAdd(&g_count, 1u);
        s_last = (c == VOL_BLOCKS - 1);
    }
    __syncthreads();
    if (!s_last) return;

    {
        const int b = tid >> 2;               // 0..63
        const int q = tid & 3;                // 296-float contiguous chunk
        const float4* p = (const float4*)(g_part + b * VOL_BLOCKS + q * 296);
        float s = 0.0f;
        #pragma unroll 4
        for (int i = 0; i < 74; i++) {
            float4 v = p[i];
            s += (v.x + v.y) + (v.z + v.w);
        }
        __shared__ float sq[64][4];
        sq[b][q] = s;
        __syncthreads();
        if (tid < 64) {
            float vol = ((sq[tid][0] + sq[tid][1]) + (sq[tid][2] + sq[tid][3]))
                        * (1.0f / 6.0f);
            // out = float(xt) * g_inv, with xt = x*2^13 -> fold 2^-13 here
            g_inv[tid] = (1.0f / cbrtf(vol)) * XT_INV;
        }
        if (tid == 0) g_count = 0;            // reset for next graph replay
    }
}

// ---------------------------------------------------------------------------
// Kernel 2: out[b][e] = float(xt[e][b]) * g_inv[b].
// 64e x 64b tiles: coalesced int4 xt reads (L2-hot after k_volume),
// smem transpose, float4 streaming writes (scalar LDS gather -> STG.128).
// ---------------------------------------------------------------------------
__global__ void k_scale(float* __restrict__ out) {
    __shared__ float ssc[64];
    __shared__ float tile[64][65];            // [b][e_local]
    const int tid = threadIdx.x;              // 256 threads
    const int e0 = blockIdx.x * 64;

    if (tid < 64) ssc[tid] = g_inv[tid];
    __syncthreads();

    // load+scale: 512 tasks = 64 e-rows x 8 int4-chunks (8 halves along b)
    #pragma unroll
    for (int k = 0; k < 2; k++) {
        int task = tid + k * 256;
        int e = task >> 3;                    // 0..63
        int c = task & 7;
        if (e0 + e < NE) {
            int4 raw = __ldg(&((const int4*)(g_xt + (e0 + e) * B))[c]);
            __half2* h = (__half2*)&raw;
            #pragma unroll
            for (int j = 0; j < 4; j++) {
                float2 f = __half22float2(h[j]);
                tile[8 * c + 2 * j][e]     = f.x * ssc[8 * c + 2 * j];
                tile[8 * c + 2 * j + 1][e] = f.y * ssc[8 * c + 2 * j + 1];
            }
        }
    }
    __syncthreads();

    // write: 1024 tasks = 64 b-rows x 16 float4 along e.
    // Build float4 from scalar LDS (row stride 65 is not 16B-aligned).
    #pragma unroll
    for (int k = 0; k < 4; k++) {
        int task = tid + k * 256;
        int b = task >> 4;                    // 0..63
        int q = task & 15;
        int e = e0 + 4 * q;
        if (e < NE) {
            float4 v = make_float4(tile[b][4 * q + 0], tile[b][4 * q + 1],
                                   tile[b][4 * q + 2], tile[b][4 * q + 3]);
            __stcs((float4*)(out + b * NE + e), v);
        }
    }
}

// ---------------------------------------------------------------------------
extern "C" void kernel_launch(void* const* d_in, const int* in_sizes, int n_in,
                              void* d_out, int out_size) {
    const float* x = (const float*)d_in[0];
    const void*  M = d_in[1];
    float*     out = (float*)d_out;

    k_pt<<<T_TILES + P_BLOCKS, 256>>>(x, M);
    k_volume<<<VOL_BLOCKS, 256>>>();
    k_scale<<<S_TILES, 256>>>(out);
}

// round 12
// speedup vs baseline: 1.4785x; 1.4785x over previous
#include <cuda_runtime.h>
#include <cuda_fp16.h>

#define B        64
#define NV       100000
#define NE       (3 * NV)        // 300000 floats per batch row
#define NT       200000          // tets
#define VOL_BLOCKS 1184          // 8 blocks/SM * 148 SMs
#define E_TILE   64
#define T_TILES  ((NE + E_TILE - 1) / E_TILE)   // 4688 (last tile: 32 rows)
#define P_BLOCKS ((NT + 255) / 256)             // 782 prep blocks
#define S_TILES  ((NE + 63) / 64)               // 4688 scale tiles

// Scratch (static device globals — no runtime allocation)
__device__ __half    g_xt[B * NE];               // transposed fp16: xt[e*64 + b]
__device__ int4      g_off4[NT];                 // {o0,o1,o2,pad}, o = idx*192
__device__ float     g_part[B * VOL_BLOCKS];     // partials, [b][blk] transposed
__device__ float     g_inv[B];                   // 1/cbrt(vol)
__device__ unsigned  g_count = 0;                // last-block counter (self-resetting)

// ---------------------------------------------------------------------------
// Kernel 0 (heterogeneous): blocks [0, T_TILES) transpose+convert x -> xt
// with 64e x 64b tiles (4 x LDG.128 per thread);
// blocks [T_TILES, ...) convert M -> fused int4 offsets.
// ---------------------------------------------------------------------------
__global__ void k_pt(const float* __restrict__ x, const void* __restrict__ Mv) {
    __shared__ float tile[E_TILE][65];
    const int tid = threadIdx.x;              // 256 threads

    if (blockIdx.x < T_TILES) {
        const int e0 = blockIdx.x * E_TILE;
        // load: 1024 tasks = 64 b x 16 float4-chunks along e
        #pragma unroll
        for (int k = 0; k < 4; k++) {
            int task = tid + k * 256;
            int b  = task >> 4;               // 0..63
            int c4 = task & 15;               // float4 chunk along e
            int e  = e0 + 4 * c4;
            if (e < NE) {
                float4 v = *(const float4*)(x + b * NE + e);
                tile[4 * c4 + 0][b] = v.x;
                tile[4 * c4 + 1][b] = v.y;
                tile[4 * c4 + 2][b] = v.z;
                tile[4 * c4 + 3][b] = v.w;
            }
        }
        __syncthreads();
        // store: 512 tasks = 64 e x 8 16B-chunks along b
        #pragma unroll
        for (int k = 0; k < 2; k++) {
            int task = tid + k * 256;
            int e = task >> 3;                // 0..63
            int c = task & 7;                 // 16B chunk along b (8 halves)
            if (e0 + e < NE) {
                __half2 h[4];
                #pragma unroll
                for (int j = 0; j < 4; j++)
                    h[j] = __floats2half2_rn(tile[e][8 * c + 2 * j],
                                             tile[e][8 * c + 2 * j + 1]);
                ((int4*)(g_xt + (e0 + e) * B))[c] = *(int4*)h;
            }
        }
    } else {
        // ---------------- index-prep path ----------------
        __shared__ int s_is64;
        if (tid == 0) {
            const int* Mi = (const int*)Mv;
            int nz = 0;
            #pragma unroll
            for (int k = 0; k < 32; k++) nz |= Mi[2 * k + 1];
            s_is64 = (nz == 0);
        }
        __syncthreads();
        int t = (blockIdx.x - T_TILES) * 256 + tid;
        if (t >= NT) return;
        int i0, i1, i2;
        if (s_is64) {
            const long long* Ml = (const long long*)Mv;
            i0 = (int)Ml[3 * t]; i1 = (int)Ml[3 * t + 1]; i2 = (int)Ml[3 * t + 2];
        } else {
            const int* Mi = (const int*)Mv;
            i0 = Mi[3 * t]; i1 = Mi[3 * t + 1]; i2 = Mi[3 * t + 2];
        }
        g_off4[t] = make_int4(i0 * (3 * B), i1 * (3 * B), i2 * (3 * B), 0);
    }
}

// ---------------------------------------------------------------------------
// Kernel 1: per-batch |det| partial sums + fused last-block reduce.
// Block = 256 threads = 32 lanes (half2 = 2 batches) x 8 tet-streams.
// det math in half2, fp32 accumulation. (Exact R8 structure, no prefetch.)
// ---------------------------------------------------------------------------
__global__ void k_volume() {
    const int tid  = threadIdx.x;
    const int lane = tid & 31;                // batch-pair id
    const int sub  = tid >> 5;                // tet stream 0..7

    float2 acc = make_float2(0.0f, 0.0f);
    const int stride = VOL_BLOCKS * 8;
    #pragma unroll 4
    for (int t = blockIdx.x * 8 + sub; t < NT; t += stride) {
        const int4 o = __ldg(&g_off4[t]);

        const __half2* p0 = (const __half2*)(g_xt + o.x) + lane;
        const __half2* p1 = (const __half2*)(g_xt + o.y) + lane;
        const __half2* p2 = (const __half2*)(g_xt + o.z) + lane;

        __half2 ax = p0[0], ay = p0[32], az = p0[64];
        __half2 bx = p1[0], by = p1[32], bz = p1[64];
        __half2 cx = p2[0], cy = p2[32], cz = p2[64];

        __half2 nbz = __hneg2(bz);
        __half2 m0 = __hfma2(by, cz, __hmul2(nbz, cy));         // by*cz - bz*cy
        __half2 m1 = __hfma2(bx, cz, __hmul2(nbz, cx));         // bx*cz - bz*cx
        __half2 m2 = __hfma2(bx, cy, __hmul2(__hneg2(by), cx)); // bx*cy - by*cx

        __half2 det = __hmul2(ax, m0);
        det = __hfma2(__hneg2(ay), m1, det);
        det = __hfma2(az, m2, det);
        det = __habs2(det);

        float2 f = __half22float2(det);
        acc.x += f.x;
        acc.y += f.y;
    }

    __shared__ float2 sred[8][32];
    sred[sub][lane] = acc;
    __syncthreads();
    if (sub == 0) {
        float2 s = acc;
        #pragma unroll
        for (int r = 1; r < 8; r++) {
            s.x += sred[r][lane].x;
            s.y += sred[r][lane].y;
        }
        g_part[(2 * lane + 0) * VOL_BLOCKS + blockIdx.x] = s.x;
        g_part[(2 * lane + 1) * VOL_BLOCKS + blockIdx.x] = s.y;
    }

    // ---- fused deterministic reduce in the last block to finish ----
    __shared__ int s_last;
    if (tid == 0) {
        __threadfence();
        unsigned c = atomicAdd(&g_count, 1u);
        s_last = (c == VOL_BLOCKS - 1);
    }
    __syncthreads();
    if (!s_last) return;

    {
        const int b = tid >> 2;               // 0..63
        const int q = tid & 3;                // 296-float contiguous chunk
        const float4* p = (const float4*)(g_part + b * VOL_BLOCKS + q * 296);
        float s = 0.0f;
        #pragma unroll 4
        for (int i = 0; i < 74; i++) {
            float4 v = p[i];
            s += (v.x + v.y) + (v.z + v.w);
        }
        __shared__ float sq[64][4];
        sq[b][q] = s;
        __syncthreads();
        if (tid < 64) {
            float vol = ((sq[tid][0] + sq[tid][1]) + (sq[tid][2] + sq[tid][3]))
                        * (1.0f / 6.0f);
            g_inv[tid] = 1.0f / cbrtf(vol);
        }
        if (tid == 0) g_count = 0;            // reset for next graph replay
    }
}

// ---------------------------------------------------------------------------
// Kernel 2: out[b][e] = float(xt[e][b]) * g_inv[b].
// 64e x 64b tiles: coalesced int4 xt reads (38MB, L2-hot after k_volume),
// smem transpose, float4 writes built from scalar LDS (stride-65 rows).
// ---------------------------------------------------------------------------
__global__ void k_scale(float* __restrict__ out) {
    __shared__ float ssc[64];
    __shared__ float tile[64][65];            // [b][e_local]
    const int tid = threadIdx.x;              // 256 threads
    const int e0 = blockIdx.x * 64;

    if (tid < 64) ssc[tid] = g_inv[tid];
    __syncthreads();

    // load+scale: 512 tasks = 64 e-rows x 8 int4-chunks (8 halves along b)
    #pragma unroll
    for (int k = 0; k < 2; k++) {
        int task = tid + k * 256;
        int e = task >> 3;                    // 0..63
        int c = task & 7;
        if (e0 + e < NE) {
            int4 raw = __ldg(&((const int4*)(g_xt + (e0 + e) * B))[c]);
            __half2* h = (__half2*)&raw;
            #pragma unroll
            for (int j = 0; j < 4; j++) {
                float2 f = __half22float2(h[j]);
                tile[8 * c + 2 * j][e]     = f.x * ssc[8 * c + 2 * j];
                tile[8 * c + 2 * j + 1][e] = f.y * ssc[8 * c + 2 * j + 1];
            }
        }
    }
    __syncthreads();

    // write: 1024 tasks = 64 b-rows x 16 float4 along e
    #pragma unroll
    for (int k = 0; k < 4; k++) {
        int task = tid + k * 256;
        int b = task >> 4;                    // 0..63
        int q = task & 15;
        int e = e0 + 4 * q;
        if (e < NE) {
            float4 v = make_float4(tile[b][4 * q + 0], tile[b][4 * q + 1],
                                   tile[b][4 * q + 2], tile[b][4 * q + 3]);
            *(float4*)(out + b * NE + e) = v;
        }
    }
}

// ---------------------------------------------------------------------------
extern "C" void kernel_launch(void* const* d_in, const int* in_sizes, int n_in,
                              void* d_out, int out_size) {
    const float* x = (const float*)d_in[0];
    const void*  M = d_in[1];
    float*     out = (float*)d_out;

    k_pt<<<T_TILES + P_BLOCKS, 256>>>(x, M);
    k_volume<<<VOL_BLOCKS, 256>>>();
    k_scale<<<S_TILES, 256>>>(out);
}